// round 15
// baseline (speedup 1.0000x reference)
#include <cuda_runtime.h>

#define NB   2
#define LQ   1024
#define LIN  4096
#define CC   256
#define MH   8
#define NP   4
#define SPTS (NB*LQ*MH*NP)   /* 65536 sampling points */

// ---------------- scratch (device globals; no allocation allowed) ----------
__device__ float g_value[NB*LIN*CC];   // (B, Lin, M, D) = 8 MiB
__device__ float g_loc[SPTS*3];        // sampling locations
__device__ float g_attw[SPTS];         // softmaxed attention weights
__device__ unsigned long long g_key[SPTS];  // packed (ordered d | idx), atomicMin

// ---------------- packed f32x2 helpers --------------------------------------
typedef unsigned long long u64;
__device__ __forceinline__ u64 pk2(float a, float b) {
    u64 r; asm("mov.b64 %0,{%1,%2};" : "=l"(r) : "f"(a), "f"(b)); return r;
}
__device__ __forceinline__ u64 ffma2(u64 a, u64 b, u64 c) {
    u64 d; asm("fma.rn.f32x2 %0,%1,%2,%3;" : "=l"(d) : "l"(a), "l"(b), "l"(c)); return d;
}
__device__ __forceinline__ float2 up2(u64 v) {
    float2 f; asm("mov.b64 {%0,%1},%2;" : "=f"(f.x), "=f"(f.y) : "l"(v)); return f;
}

// ---------------- tiled SGEMM-NT 64x64, K=256, BK=16, 256 thr, 4x4 ----------
// proj GEMM 2048x128 with fused location/softmax epilogue + g_key init
template<int EPI>
__global__ __launch_bounds__(256)
void sgemm_nt(const float* __restrict__ A,
              const float* __restrict__ W1, const float* __restrict__ W2, int wsplit,
              const float* __restrict__ b1, const float* __restrict__ b2,
              float* __restrict__ Out, int N,
              const float* __restrict__ qpts)
{
    __shared__ float As[16][68];
    __shared__ float Bs[16][68];
    const int tid = threadIdx.x;
    const int tx = tid & 15, ty = tid >> 4;
    const int rowBase = blockIdx.y * 64;
    const int colBase = blockIdx.x * 64;
    const int lr = tid >> 2;
    const int lc = (tid & 3) * 4;

    const float* Aptr = A + (rowBase + lr) * 256 + lc;
    const int wrow = colBase + lr;
    const float* Wptr = (wrow < wsplit) ? (W1 + wrow * 256 + lc)
                                        : (W2 + (wrow - wsplit) * 256 + lc);
    float4 ra = *(const float4*)Aptr;
    float4 rw = *(const float4*)Wptr;

    u64 acc[4][2];
    #pragma unroll
    for (int i = 0; i < 4; i++) { acc[i][0] = 0ull; acc[i][1] = 0ull; }

    for (int kt = 0; kt < 256; kt += 16) {
        As[lc+0][lr] = ra.x; As[lc+1][lr] = ra.y; As[lc+2][lr] = ra.z; As[lc+3][lr] = ra.w;
        Bs[lc+0][lr] = rw.x; Bs[lc+1][lr] = rw.y; Bs[lc+2][lr] = rw.z; Bs[lc+3][lr] = rw.w;
        __syncthreads();
        if (kt < 240) {
            ra = *(const float4*)(Aptr + kt + 16);
            rw = *(const float4*)(Wptr + kt + 16);
        }
        #pragma unroll
        for (int k = 0; k < 16; k++) {
            float4 av = *(const float4*)&As[k][ty * 4];
            float4 bv = *(const float4*)&Bs[k][tx * 4];
            u64 b01 = pk2(bv.x, bv.y), b23 = pk2(bv.z, bv.w);
            u64 a0 = pk2(av.x, av.x), a1 = pk2(av.y, av.y);
            u64 a2 = pk2(av.z, av.z), a3 = pk2(av.w, av.w);
            acc[0][0] = ffma2(a0, b01, acc[0][0]); acc[0][1] = ffma2(a0, b23, acc[0][1]);
            acc[1][0] = ffma2(a1, b01, acc[1][0]); acc[1][1] = ffma2(a1, b23, acc[1][1]);
            acc[2][0] = ffma2(a2, b01, acc[2][0]); acc[2][1] = ffma2(a2, b23, acc[2][1]);
            acc[3][0] = ffma2(a3, b01, acc[3][0]); acc[3][1] = ffma2(a3, b23, acc[3][1]);
        }
        __syncthreads();
    }

    const int c0 = colBase + tx * 4;
    float bias[4];
    #pragma unroll
    for (int j = 0; j < 4; j++) {
        int c = c0 + j;
        bias[j] = (c < wsplit) ? b1[c] : b2[c - wsplit];
    }

    #pragma unroll
    for (int i = 0; i < 4; i++) {
        const int r = rowBase + ty * 4 + i;
        float2 v01 = up2(acc[i][0]);
        float2 v23 = up2(acc[i][1]);
        float v[4] = { v01.x + bias[0], v01.y + bias[1],
                       v23.x + bias[2], v23.y + bias[3] };
        if (EPI == 0) {
            *(float4*)&Out[r * N + c0] = make_float4(v[0], v[1], v[2], v[3]);
        } else {
            if (c0 < 96) {
                #pragma unroll
                for (int j = 0; j < 4; j++) {
                    int c = c0 + j;
                    g_loc[r * 96 + c] = v[j] + qpts[r * 3 + (c % 3)];
                }
            } else {
                float m0 = fmaxf(fmaxf(v[0], v[1]), fmaxf(v[2], v[3]));
                float e0 = __expf(v[0] - m0), e1 = __expf(v[1] - m0);
                float e2 = __expf(v[2] - m0), e3 = __expf(v[3] - m0);
                float inv = 1.0f / (e0 + e1 + e2 + e3);
                int base = r * 32 + (c0 - 96);
                g_attw[base + 0] = e0 * inv;
                g_attw[base + 1] = e1 * inv;
                g_attw[base + 2] = e2 * inv;
                g_attw[base + 3] = e3 * inv;
                // free init of the atomicMin key array (exactly these 32 sp/row)
                g_key[base + 0] = ~0ull;
                g_key[base + 1] = ~0ull;
                g_key[base + 2] = ~0ull;
                g_key[base + 3] = ~0ull;
            }
        }
    }
}

// ---------------- tiled SGEMM-NT 128x128, K=256, BK=16, 256 thr, 8x8 --------
__global__ __launch_bounds__(256)
void sgemm128(const float* __restrict__ A, const float* __restrict__ W,
              const float* __restrict__ bias, float* __restrict__ Out, int N)
{
    __shared__ float As[16][128];
    __shared__ float Bs[16][128];
    const int tid = threadIdx.x;
    const int tx = tid & 15;
    const int ty = tid >> 4;
    const int rowBase = blockIdx.y * 128;
    const int colBase = blockIdx.x * 128;

    const int lr = tid >> 1;
    const int lk = (tid & 1) * 8;
    const float* Aptr = A + (rowBase + lr) * 256 + lk;
    const float* Wptr = W + (colBase + lr) * 256 + lk;
    float4 ra0 = *(const float4*)Aptr;
    float4 ra1 = *(const float4*)(Aptr + 4);
    float4 rw0 = *(const float4*)Wptr;
    float4 rw1 = *(const float4*)(Wptr + 4);

    u64 acc[8][4];
    #pragma unroll
    for (int i = 0; i < 8; i++)
        #pragma unroll
        for (int j = 0; j < 4; j++) acc[i][j] = 0ull;

    for (int kt = 0; kt < 256; kt += 16) {
        As[lk+0][lr] = ra0.x; As[lk+1][lr] = ra0.y; As[lk+2][lr] = ra0.z; As[lk+3][lr] = ra0.w;
        As[lk+4][lr] = ra1.x; As[lk+5][lr] = ra1.y; As[lk+6][lr] = ra1.z; As[lk+7][lr] = ra1.w;
        Bs[lk+0][lr] = rw0.x; Bs[lk+1][lr] = rw0.y; Bs[lk+2][lr] = rw0.z; Bs[lk+3][lr] = rw0.w;
        Bs[lk+4][lr] = rw1.x; Bs[lk+5][lr] = rw1.y; Bs[lk+6][lr] = rw1.z; Bs[lk+7][lr] = rw1.w;
        __syncthreads();
        if (kt < 240) {
            ra0 = *(const float4*)(Aptr + kt + 16);
            ra1 = *(const float4*)(Aptr + kt + 20);
            rw0 = *(const float4*)(Wptr + kt + 16);
            rw1 = *(const float4*)(Wptr + kt + 20);
        }
        #pragma unroll
        for (int k = 0; k < 16; k++) {
            float4 a0 = *(const float4*)&As[k][ty * 8];
            float4 a1 = *(const float4*)&As[k][ty * 8 + 4];
            float4 b0 = *(const float4*)&Bs[k][tx * 8];
            float4 b1 = *(const float4*)&Bs[k][tx * 8 + 4];
            u64 bp[4] = { pk2(b0.x, b0.y), pk2(b0.z, b0.w),
                          pk2(b1.x, b1.y), pk2(b1.z, b1.w) };
            float av[8] = { a0.x, a0.y, a0.z, a0.w, a1.x, a1.y, a1.z, a1.w };
            #pragma unroll
            for (int i = 0; i < 8; i++) {
                u64 ap = pk2(av[i], av[i]);
                #pragma unroll
                for (int j = 0; j < 4; j++)
                    acc[i][j] = ffma2(ap, bp[j], acc[i][j]);
            }
        }
        __syncthreads();
    }

    const int c0 = colBase + tx * 8;
    float4 bia0 = *(const float4*)&bias[c0];
    float4 bia1 = *(const float4*)&bias[c0 + 4];
    #pragma unroll
    for (int i = 0; i < 8; i++) {
        const int r = rowBase + ty * 8 + i;
        float2 v0 = up2(acc[i][0]), v1 = up2(acc[i][1]);
        float2 v2 = up2(acc[i][2]), v3 = up2(acc[i][3]);
        *(float4*)&Out[r * N + c0] =
            make_float4(v0.x + bia0.x, v0.y + bia0.y, v1.x + bia0.z, v1.y + bia0.w);
        *(float4*)&Out[r * N + c0 + 4] =
            make_float4(v2.x + bia1.x, v2.y + bia1.y, v3.x + bia1.z, v3.y + bia1.w);
    }
}

// ---------------- brute-force 1-NN, min-only tracking (round-9 body) --------
// 256 blocks = 64 s-blocks x 4 candidate quarters; 4 sampling points/thread.
// Winner published as atomicMin on packed key (ordered_dist<<32)|global_idx:
// exact argmin with lowest-index tie-break, combine-free for the consumer.
__global__ __launch_bounds__(256)
void knn_kernel(const float* __restrict__ ipts)
{
    __shared__ __align__(16) float xs[1024];
    __shared__ __align__(16) float ys[1024];
    __shared__ __align__(16) float zs[1024];
    __shared__ __align__(16) float wsq[1024];

    const int tid  = threadIdx.x;
    const int sblk = blockIdx.x >> 2;      // 0..63
    const int q    = blockIdx.x & 3;       // candidate quarter
    const int sbase = sblk * 1024;
    const int b = sbase >> 15;
    const int cbase = b * LIN + q * 1024;

    for (int i = tid; i < 1024; i += 256) {
        float x = ipts[(cbase + i) * 3 + 0];
        float y = ipts[(cbase + i) * 3 + 1];
        float z = ipts[(cbase + i) * 3 + 2];
        xs[i] = x; ys[i] = y; zs[i] = z;
        wsq[i] = x * x + y * y + z * z;
    }
    __syncthreads();

    int   s[4], bg[4];
    float best[4];
    u64 ax2[4], ay2[4], az2[4];
    #pragma unroll
    for (int k = 0; k < 4; k++) {
        s[k] = sbase + k * 256 + tid;
        float sx = g_loc[3 * s[k] + 0];
        float sy = g_loc[3 * s[k] + 1];
        float sz = g_loc[3 * s[k] + 2];
        float ax = -2.0f * sx, ay = -2.0f * sy, az = -2.0f * sz;
        ax2[k] = pk2(ax, ax); ay2[k] = pk2(ay, ay); az2[k] = pk2(az, az);
        best[k] = 3.4e38f; bg[k] = 0;
    }

    const u64* X  = (const u64*)xs;
    const u64* Y  = (const u64*)ys;
    const u64* Z  = (const u64*)zs;
    const u64* Wq = (const u64*)wsq;

    // group g = candidates 4g..4g+3 (two u64 pairs)
    #pragma unroll 4
    for (int g = 0; g < 256; g++) {
        u64 x0 = X[2*g], x1 = X[2*g+1];
        u64 y0 = Y[2*g], y1 = Y[2*g+1];
        u64 z0 = Z[2*g], z1 = Z[2*g+1];
        u64 w0 = Wq[2*g], w1 = Wq[2*g+1];
        #pragma unroll
        for (int k = 0; k < 4; k++) {
            u64 da = ffma2(x0, ax2[k], w0);
            da = ffma2(y0, ay2[k], da);
            da = ffma2(z0, az2[k], da);
            u64 db = ffma2(x1, ax2[k], w1);
            db = ffma2(y1, ay2[k], db);
            db = ffma2(z1, az2[k], db);
            float2 fa = up2(da), fb = up2(db);
            float m = fminf(fminf(fa.x, fa.y), fminf(fb.x, fb.y));
            if (m < best[k]) { best[k] = m; bg[k] = g; }   // strict <: earliest group
        }
    }

    // post-pass: resolve exact slot (bit-identical recompute), publish key
    #pragma unroll
    for (int k = 0; k < 4; k++) {
        int g = bg[k];
        u64 da = ffma2(X[2*g],   ax2[k], Wq[2*g]);
        da = ffma2(Y[2*g],   ay2[k], da);
        da = ffma2(Z[2*g],   az2[k], da);
        u64 db = ffma2(X[2*g+1], ax2[k], Wq[2*g+1]);
        db = ffma2(Y[2*g+1], ay2[k], db);
        db = ffma2(Z[2*g+1], az2[k], db);
        float2 fa = up2(da), fb = up2(db);
        int idx = 4*g + 3;
        if (fb.x == best[k]) idx = 4*g + 2;   // reverse order: first-equal wins
        if (fa.y == best[k]) idx = 4*g + 1;
        if (fa.x == best[k]) idx = 4*g + 0;
        // monotone float -> ordered-uint transform (handles negative d)
        unsigned ud = __float_as_uint(best[k]);
        ud = ((int)ud < 0) ? ~ud : (ud | 0x80000000u);
        u64 key = ((u64)ud << 32) | (unsigned)(q * 1024 + idx);
        atomicMin(&g_key[s[k]], key);   // min -> smallest d, tie -> lowest idx
    }
}

// ---------------- fused gather + output projection ---------------------------
// 256 blocks; block = 8 query rows (bq). Phase 1: warp w gathers row bq0+w
// (8 m x 32 d) into smem. Phase 2: 8x256 @ Wo^T GEMM, Wo staged via smem
// (L2-resident). Replaces gather_kernel + sgemm_nt<0> + g_mid round-trip.
__global__ __launch_bounds__(256)
void gather_out(const float* __restrict__ Wo, const float* __restrict__ bo,
                float* __restrict__ out)
{
    __shared__ float As[8][256];      // gathered mid rows
    __shared__ float Bs[16][264];     // Wo^T staging tile [k][c]
    const int tid = threadIdx.x;
    const int w = tid >> 5, lane = tid & 31;
    const int bq0 = blockIdx.x * 8;

    // ---- phase 1: gather row bq = bq0 + w ----
    {
        const int bq = bq0 + w;
        const int b = bq >> 10;
        #pragma unroll 2
        for (int m = 0; m < 8; m++) {
            const int base = bq * 32 + m * 4;
            float4 aw = *(const float4*)&g_attw[base];
            ulonglong2 k01 = *(const ulonglong2*)&g_key[base];
            ulonglong2 k23 = *(const ulonglong2*)&g_key[base + 2];
            int l0 = (int)(unsigned)(k01.x & 0xffffffffu);
            int l1 = (int)(unsigned)(k01.y & 0xffffffffu);
            int l2 = (int)(unsigned)(k23.x & 0xffffffffu);
            int l3 = (int)(unsigned)(k23.y & 0xffffffffu);
            float acc = aw.x * g_value[(b * LIN + l0) * CC + m * 32 + lane];
            acc += aw.y * g_value[(b * LIN + l1) * CC + m * 32 + lane];
            acc += aw.z * g_value[(b * LIN + l2) * CC + m * 32 + lane];
            acc += aw.w * g_value[(b * LIN + l3) * CC + m * 32 + lane];
            As[w][m * 32 + lane] = acc;
        }
    }

    // ---- phase 2: out[bq][c] = sum_k As[r][k] * Wo[c][k] + bo[c] ----
    const int r  = tid >> 5;          // row 0..7 (= warp)
    const int cg = tid & 31;          // col group: cols cg*8..cg*8+7
    u64 acc[4] = {0ull, 0ull, 0ull, 0ull};

    for (int kt = 0; kt < 256; kt += 16) {
        __syncthreads();              // first iter also covers phase-1 As writes
        {   // stage Wo[c][kt..kt+15] -> Bs[0..15][c], c = tid
            const float4* wrow = (const float4*)(Wo + tid * 256 + kt);
            float4 w0 = wrow[0], w1 = wrow[1], w2 = wrow[2], w3 = wrow[3];
            Bs[ 0][tid] = w0.x; Bs[ 1][tid] = w0.y; Bs[ 2][tid] = w0.z; Bs[ 3][tid] = w0.w;
            Bs[ 4][tid] = w1.x; Bs[ 5][tid] = w1.y; Bs[ 6][tid] = w1.z; Bs[ 7][tid] = w1.w;
            Bs[ 8][tid] = w2.x; Bs[ 9][tid] = w2.y; Bs[10][tid] = w2.z; Bs[11][tid] = w2.w;
            Bs[12][tid] = w3.x; Bs[13][tid] = w3.y; Bs[14][tid] = w3.z; Bs[15][tid] = w3.w;
        }
        __syncthreads();
        #pragma unroll
        for (int k = 0; k < 16; k++) {
            float a = As[r][kt + k];          // warp-uniform broadcast
            u64 a2 = pk2(a, a);
            float4 b0 = *(const float4*)&Bs[k][cg * 8];
            float4 b1 = *(const float4*)&Bs[k][cg * 8 + 4];
            acc[0] = ffma2(a2, pk2(b0.x, b0.y), acc[0]);
            acc[1] = ffma2(a2, pk2(b0.z, b0.w), acc[1]);
            acc[2] = ffma2(a2, pk2(b1.x, b1.y), acc[2]);
            acc[3] = ffma2(a2, pk2(b1.z, b1.w), acc[3]);
        }
    }

    const int c0 = cg * 8;
    float4 bo0 = *(const float4*)&bo[c0];
    float4 bo1 = *(const float4*)&bo[c0 + 4];
    float2 v0 = up2(acc[0]), v1 = up2(acc[1]);
    float2 v2 = up2(acc[2]), v3 = up2(acc[3]);
    float* orow = out + (bq0 + r) * 256 + c0;
    *(float4*)orow =
        make_float4(v0.x + bo0.x, v0.y + bo0.y, v1.x + bo0.z, v1.y + bo0.w);
    *(float4*)(orow + 4) =
        make_float4(v2.x + bo1.x, v2.y + bo1.y, v3.x + bo1.z, v3.y + bo1.w);
}

// ---------------------------------------------------------------------------
extern "C" void kernel_launch(void* const* d_in, const int* in_sizes, int n_in,
                              void* d_out, int out_size) {
    const float* query = (const float*)d_in[0];
    const float* qpts  = (const float*)d_in[1];
    const float* inp   = (const float*)d_in[2];
    const float* ipts  = (const float*)d_in[3];
    const float* Wv    = (const float*)d_in[4];
    const float* bv    = (const float*)d_in[5];
    const float* Ws    = (const float*)d_in[6];
    const float* bs    = (const float*)d_in[7];
    const float* Wa    = (const float*)d_in[8];
    const float* ba    = (const float*)d_in[9];
    const float* Wo    = (const float*)d_in[10];
    const float* bo    = (const float*)d_in[11];
    float* out = (float*)d_out;

    float *p_value;
    cudaGetSymbolAddress((void**)&p_value, g_value);

    static cudaStream_t s1 = nullptr;
    static cudaEvent_t evFork = nullptr, evJoin = nullptr;
    if (!s1) {
        cudaStreamCreateWithFlags(&s1, cudaStreamNonBlocking);
        cudaEventCreateWithFlags(&evFork, cudaEventDisableTiming);
        cudaEventCreateWithFlags(&evJoin, cudaEventDisableTiming);
    }

    // fork: value GEMM on side stream (independent of proj/knn)
    cudaEventRecord(evFork, 0);
    cudaStreamWaitEvent(s1, evFork, 0);
    sgemm128<<<dim3(2, 64), 256, 0, s1>>>(inp, Wv, bv, p_value, 256);
    cudaEventRecord(evJoin, s1);

    // main stream: proj (-> g_loc, g_attw, g_key init), then KNN (atomicMin)
    sgemm_nt<1><<<dim3(2, 32), 256>>>(query, Ws, Wa, 96, bs, ba,
                                      nullptr, 128, qpts);
    knn_kernel<<<256, 256>>>(ipts);

    // join: fused gather + output projection needs knn keys and g_value
    cudaStreamWaitEvent(0, evJoin, 0);
    gather_out<<<256, 256>>>(Wo, bo, out);
}

// round 16
// speedup vs baseline: 1.3921x; 1.3921x over previous
#include <cuda_runtime.h>

#define NB   2
#define LQ   1024
#define LIN  4096
#define CC   256
#define MH   8
#define NP   4
#define SPTS (NB*LQ*MH*NP)   /* 65536 sampling points */

// ---------------- scratch (device globals; no allocation allowed) ----------
__device__ float g_value[NB*LIN*CC];   // (B, Lin, M, D) = 8 MiB
__device__ float g_loc[SPTS*3];        // sampling locations
__device__ float g_attw[SPTS];         // softmaxed attention weights
__device__ unsigned long long g_key[SPTS];  // packed (ordered d | idx), atomicMin
__device__ float g_mid[NB*LQ*CC];      // pre-output-projection features

// ---------------- packed f32x2 helpers --------------------------------------
typedef unsigned long long u64;
__device__ __forceinline__ u64 pk2(float a, float b) {
    u64 r; asm("mov.b64 %0,{%1,%2};" : "=l"(r) : "f"(a), "f"(b)); return r;
}
__device__ __forceinline__ u64 ffma2(u64 a, u64 b, u64 c) {
    u64 d; asm("fma.rn.f32x2 %0,%1,%2,%3;" : "=l"(d) : "l"(a), "l"(b), "l"(c)); return d;
}
__device__ __forceinline__ float2 up2(u64 v) {
    float2 f; asm("mov.b64 {%0,%1},%2;" : "=f"(f.x), "=f"(f.y) : "l"(v)); return f;
}

// ---------------- tiled SGEMM-NT 64x64, K=256, BK=16, 256 thr, 4x4 ----------
// EPI=0: plain (out-projection). EPI=1: proj epilogue (loc/softmax/key-init).
template<int EPI>
__global__ __launch_bounds__(256)
void sgemm_nt(const float* __restrict__ A,
              const float* __restrict__ W1, const float* __restrict__ W2, int wsplit,
              const float* __restrict__ b1, const float* __restrict__ b2,
              float* __restrict__ Out, int N,
              const float* __restrict__ qpts)
{
    __shared__ float As[16][68];
    __shared__ float Bs[16][68];
    const int tid = threadIdx.x;
    const int tx = tid & 15, ty = tid >> 4;
    const int rowBase = blockIdx.y * 64;
    const int colBase = blockIdx.x * 64;
    const int lr = tid >> 2;
    const int lc = (tid & 3) * 4;

    const float* Aptr = A + (rowBase + lr) * 256 + lc;
    const int wrow = colBase + lr;
    const float* Wptr = (wrow < wsplit) ? (W1 + wrow * 256 + lc)
                                        : (W2 + (wrow - wsplit) * 256 + lc);
    float4 ra = *(const float4*)Aptr;
    float4 rw = *(const float4*)Wptr;

    u64 acc[4][2];
    #pragma unroll
    for (int i = 0; i < 4; i++) { acc[i][0] = 0ull; acc[i][1] = 0ull; }

    for (int kt = 0; kt < 256; kt += 16) {
        As[lc+0][lr] = ra.x; As[lc+1][lr] = ra.y; As[lc+2][lr] = ra.z; As[lc+3][lr] = ra.w;
        Bs[lc+0][lr] = rw.x; Bs[lc+1][lr] = rw.y; Bs[lc+2][lr] = rw.z; Bs[lc+3][lr] = rw.w;
        __syncthreads();
        if (kt < 240) {
            ra = *(const float4*)(Aptr + kt + 16);
            rw = *(const float4*)(Wptr + kt + 16);
        }
        #pragma unroll
        for (int k = 0; k < 16; k++) {
            float4 av = *(const float4*)&As[k][ty * 4];
            float4 bv = *(const float4*)&Bs[k][tx * 4];
            u64 b01 = pk2(bv.x, bv.y), b23 = pk2(bv.z, bv.w);
            u64 a0 = pk2(av.x, av.x), a1 = pk2(av.y, av.y);
            u64 a2 = pk2(av.z, av.z), a3 = pk2(av.w, av.w);
            acc[0][0] = ffma2(a0, b01, acc[0][0]); acc[0][1] = ffma2(a0, b23, acc[0][1]);
            acc[1][0] = ffma2(a1, b01, acc[1][0]); acc[1][1] = ffma2(a1, b23, acc[1][1]);
            acc[2][0] = ffma2(a2, b01, acc[2][0]); acc[2][1] = ffma2(a2, b23, acc[2][1]);
            acc[3][0] = ffma2(a3, b01, acc[3][0]); acc[3][1] = ffma2(a3, b23, acc[3][1]);
        }
        __syncthreads();
    }

    const int c0 = colBase + tx * 4;
    float bias[4];
    #pragma unroll
    for (int j = 0; j < 4; j++) {
        int c = c0 + j;
        bias[j] = (c < wsplit) ? b1[c] : b2[c - wsplit];
    }

    #pragma unroll
    for (int i = 0; i < 4; i++) {
        const int r = rowBase + ty * 4 + i;
        float2 v01 = up2(acc[i][0]);
        float2 v23 = up2(acc[i][1]);
        float v[4] = { v01.x + bias[0], v01.y + bias[1],
                       v23.x + bias[2], v23.y + bias[3] };
        if (EPI == 0) {
            *(float4*)&Out[r * N + c0] = make_float4(v[0], v[1], v[2], v[3]);
        } else {
            if (c0 < 96) {
                #pragma unroll
                for (int j = 0; j < 4; j++) {
                    int c = c0 + j;
                    g_loc[r * 96 + c] = v[j] + qpts[r * 3 + (c % 3)];
                }
            } else {
                float m0 = fmaxf(fmaxf(v[0], v[1]), fmaxf(v[2], v[3]));
                float e0 = __expf(v[0] - m0), e1 = __expf(v[1] - m0);
                float e2 = __expf(v[2] - m0), e3 = __expf(v[3] - m0);
                float inv = 1.0f / (e0 + e1 + e2 + e3);
                int base = r * 32 + (c0 - 96);
                g_attw[base + 0] = e0 * inv;
                g_attw[base + 1] = e1 * inv;
                g_attw[base + 2] = e2 * inv;
                g_attw[base + 3] = e3 * inv;
                // free init of the atomicMin key array (exactly these 32 sp/row)
                g_key[base + 0] = ~0ull;
                g_key[base + 1] = ~0ull;
                g_key[base + 2] = ~0ull;
                g_key[base + 3] = ~0ull;
            }
        }
    }
}

// ---------------- tiled SGEMM-NT 128x128, K=256, BK=16, 256 thr, 8x8 --------
__global__ __launch_bounds__(256)
void sgemm128(const float* __restrict__ A, const float* __restrict__ W,
              const float* __restrict__ bias, float* __restrict__ Out, int N)
{
    __shared__ float As[16][128];
    __shared__ float Bs[16][128];
    const int tid = threadIdx.x;
    const int tx = tid & 15;
    const int ty = tid >> 4;
    const int rowBase = blockIdx.y * 128;
    const int colBase = blockIdx.x * 128;

    const int lr = tid >> 1;
    const int lk = (tid & 1) * 8;
    const float* Aptr = A + (rowBase + lr) * 256 + lk;
    const float* Wptr = W + (colBase + lr) * 256 + lk;
    float4 ra0 = *(const float4*)Aptr;
    float4 ra1 = *(const float4*)(Aptr + 4);
    float4 rw0 = *(const float4*)Wptr;
    float4 rw1 = *(const float4*)(Wptr + 4);

    u64 acc[8][4];
    #pragma unroll
    for (int i = 0; i < 8; i++)
        #pragma unroll
        for (int j = 0; j < 4; j++) acc[i][j] = 0ull;

    for (int kt = 0; kt < 256; kt += 16) {
        As[lk+0][lr] = ra0.x; As[lk+1][lr] = ra0.y; As[lk+2][lr] = ra0.z; As[lk+3][lr] = ra0.w;
        As[lk+4][lr] = ra1.x; As[lk+5][lr] = ra1.y; As[lk+6][lr] = ra1.z; As[lk+7][lr] = ra1.w;
        Bs[lk+0][lr] = rw0.x; Bs[lk+1][lr] = rw0.y; Bs[lk+2][lr] = rw0.z; Bs[lk+3][lr] = rw0.w;
        Bs[lk+4][lr] = rw1.x; Bs[lk+5][lr] = rw1.y; Bs[lk+6][lr] = rw1.z; Bs[lk+7][lr] = rw1.w;
        __syncthreads();
        if (kt < 240) {
            ra0 = *(const float4*)(Aptr + kt + 16);
            ra1 = *(const float4*)(Aptr + kt + 20);
            rw0 = *(const float4*)(Wptr + kt + 16);
            rw1 = *(const float4*)(Wptr + kt + 20);
        }
        #pragma unroll
        for (int k = 0; k < 16; k++) {
            float4 a0 = *(const float4*)&As[k][ty * 8];
            float4 a1 = *(const float4*)&As[k][ty * 8 + 4];
            float4 b0 = *(const float4*)&Bs[k][tx * 8];
            float4 b1 = *(const float4*)&Bs[k][tx * 8 + 4];
            u64 bp[4] = { pk2(b0.x, b0.y), pk2(b0.z, b0.w),
                          pk2(b1.x, b1.y), pk2(b1.z, b1.w) };
            float av[8] = { a0.x, a0.y, a0.z, a0.w, a1.x, a1.y, a1.z, a1.w };
            #pragma unroll
            for (int i = 0; i < 8; i++) {
                u64 ap = pk2(av[i], av[i]);
                #pragma unroll
                for (int j = 0; j < 4; j++)
                    acc[i][j] = ffma2(ap, bp[j], acc[i][j]);
            }
        }
        __syncthreads();
    }

    const int c0 = colBase + tx * 8;
    float4 bia0 = *(const float4*)&bias[c0];
    float4 bia1 = *(const float4*)&bias[c0 + 4];
    #pragma unroll
    for (int i = 0; i < 8; i++) {
        const int r = rowBase + ty * 8 + i;
        float2 v0 = up2(acc[i][0]), v1 = up2(acc[i][1]);
        float2 v2 = up2(acc[i][2]), v3 = up2(acc[i][3]);
        *(float4*)&Out[r * N + c0] =
            make_float4(v0.x + bia0.x, v0.y + bia0.y, v1.x + bia0.z, v1.y + bia0.w);
        *(float4*)&Out[r * N + c0 + 4] =
            make_float4(v2.x + bia1.x, v2.y + bia1.y, v3.x + bia1.z, v3.y + bia1.w);
    }
}

// ---------------- brute-force 1-NN, min-only tracking (round-9 body) --------
// 256 blocks = 64 s-blocks x 4 candidate quarters; 4 sampling points/thread.
// Winner published via atomicMin on packed key (ordered_dist<<32)|global_idx:
// exact argmin with lowest-index tie-break, combine-free for the consumer.
__global__ __launch_bounds__(256)
void knn_kernel(const float* __restrict__ ipts)
{
    __shared__ __align__(16) float xs[1024];
    __shared__ __align__(16) float ys[1024];
    __shared__ __align__(16) float zs[1024];
    __shared__ __align__(16) float wsq[1024];

    const int tid  = threadIdx.x;
    const int sblk = blockIdx.x >> 2;      // 0..63
    const int q    = blockIdx.x & 3;       // candidate quarter
    const int sbase = sblk * 1024;
    const int b = sbase >> 15;
    const int cbase = b * LIN + q * 1024;

    for (int i = tid; i < 1024; i += 256) {
        float x = ipts[(cbase + i) * 3 + 0];
        float y = ipts[(cbase + i) * 3 + 1];
        float z = ipts[(cbase + i) * 3 + 2];
        xs[i] = x; ys[i] = y; zs[i] = z;
        wsq[i] = x * x + y * y + z * z;
    }
    __syncthreads();

    int   s[4], bg[4];
    float best[4];
    u64 ax2[4], ay2[4], az2[4];
    #pragma unroll
    for (int k = 0; k < 4; k++) {
        s[k] = sbase + k * 256 + tid;
        float sx = g_loc[3 * s[k] + 0];
        float sy = g_loc[3 * s[k] + 1];
        float sz = g_loc[3 * s[k] + 2];
        float ax = -2.0f * sx, ay = -2.0f * sy, az = -2.0f * sz;
        ax2[k] = pk2(ax, ax); ay2[k] = pk2(ay, ay); az2[k] = pk2(az, az);
        best[k] = 3.4e38f; bg[k] = 0;
    }

    const u64* X  = (const u64*)xs;
    const u64* Y  = (const u64*)ys;
    const u64* Z  = (const u64*)zs;
    const u64* Wq = (const u64*)wsq;

    // group g = candidates 4g..4g+3 (two u64 pairs)
    #pragma unroll 4
    for (int g = 0; g < 256; g++) {
        u64 x0 = X[2*g], x1 = X[2*g+1];
        u64 y0 = Y[2*g], y1 = Y[2*g+1];
        u64 z0 = Z[2*g], z1 = Z[2*g+1];
        u64 w0 = Wq[2*g], w1 = Wq[2*g+1];
        #pragma unroll
        for (int k = 0; k < 4; k++) {
            u64 da = ffma2(x0, ax2[k], w0);
            da = ffma2(y0, ay2[k], da);
            da = ffma2(z0, az2[k], da);
            u64 db = ffma2(x1, ax2[k], w1);
            db = ffma2(y1, ay2[k], db);
            db = ffma2(z1, az2[k], db);
            float2 fa = up2(da), fb = up2(db);
            float m = fminf(fminf(fa.x, fa.y), fminf(fb.x, fb.y));
            if (m < best[k]) { best[k] = m; bg[k] = g; }   // strict <: earliest group
        }
    }

    // post-pass: resolve exact slot (bit-identical recompute), publish key
    #pragma unroll
    for (int k = 0; k < 4; k++) {
        int g = bg[k];
        u64 da = ffma2(X[2*g],   ax2[k], Wq[2*g]);
        da = ffma2(Y[2*g],   ay2[k], da);
        da = ffma2(Z[2*g],   az2[k], da);
        u64 db = ffma2(X[2*g+1], ax2[k], Wq[2*g+1]);
        db = ffma2(Y[2*g+1], ay2[k], db);
        db = ffma2(Z[2*g+1], az2[k], db);
        float2 fa = up2(da), fb = up2(db);
        int idx = 4*g + 3;
        if (fb.x == best[k]) idx = 4*g + 2;   // reverse order: first-equal wins
        if (fa.y == best[k]) idx = 4*g + 1;
        if (fa.x == best[k]) idx = 4*g + 0;
        // monotone float -> ordered-uint transform (handles negative d)
        unsigned ud = __float_as_uint(best[k]);
        ud = ((int)ud < 0) ? ~ud : (ud | 0x80000000u);
        u64 key = ((u64)ud << 32) | (unsigned)(q * 1024 + idx);
        atomicMin(&g_key[s[k]], key);   // min -> smallest d, tie -> lowest idx
    }
}

// ---------------- gather + weighted sum (combine-free via g_key) ------------
__global__ __launch_bounds__(256)
void gather_kernel()
{
    const int g    = (blockIdx.x * 256 + threadIdx.x) >> 5;  // bq*8 + m
    const int lane = threadIdx.x & 31;
    const int m  = g & 7;
    const int bq = g >> 3;
    const int b  = bq >> 10;
    const int base = bq * 32 + m * 4;
    const float4 aw = *(const float4*)&g_attw[base];
    ulonglong2 k01 = *(const ulonglong2*)&g_key[base];
    ulonglong2 k23 = *(const ulonglong2*)&g_key[base + 2];
    int l0 = (int)(unsigned)(k01.x & 0xffffffffu);
    int l1 = (int)(unsigned)(k01.y & 0xffffffffu);
    int l2 = (int)(unsigned)(k23.x & 0xffffffffu);
    int l3 = (int)(unsigned)(k23.y & 0xffffffffu);
    float acc = aw.x * g_value[(b * LIN + l0) * CC + m * 32 + lane];
    acc += aw.y * g_value[(b * LIN + l1) * CC + m * 32 + lane];
    acc += aw.z * g_value[(b * LIN + l2) * CC + m * 32 + lane];
    acc += aw.w * g_value[(b * LIN + l3) * CC + m * 32 + lane];
    g_mid[bq * CC + m * 32 + lane] = acc;
}

// ---------------------------------------------------------------------------
extern "C" void kernel_launch(void* const* d_in, const int* in_sizes, int n_in,
                              void* d_out, int out_size) {
    const float* query = (const float*)d_in[0];
    const float* qpts  = (const float*)d_in[1];
    const float* inp   = (const float*)d_in[2];
    const float* ipts  = (const float*)d_in[3];
    const float* Wv    = (const float*)d_in[4];
    const float* bv    = (const float*)d_in[5];
    const float* Ws    = (const float*)d_in[6];
    const float* bs    = (const float*)d_in[7];
    const float* Wa    = (const float*)d_in[8];
    const float* ba    = (const float*)d_in[9];
    const float* Wo    = (const float*)d_in[10];
    const float* bo    = (const float*)d_in[11];
    float* out = (float*)d_out;

    float *p_value, *p_mid;
    cudaGetSymbolAddress((void**)&p_value, g_value);
    cudaGetSymbolAddress((void**)&p_mid,   g_mid);

    const int BIG = 1 << 30;

    static cudaStream_t s1 = nullptr;
    static cudaEvent_t evFork = nullptr, evJoin = nullptr;
    if (!s1) {
        cudaStreamCreateWithFlags(&s1, cudaStreamNonBlocking);
        cudaEventCreateWithFlags(&evFork, cudaEventDisableTiming);
        cudaEventCreateWithFlags(&evJoin, cudaEventDisableTiming);
    }

    // fork: value GEMM on side stream (independent of proj/knn)
    cudaEventRecord(evFork, 0);
    cudaStreamWaitEvent(s1, evFork, 0);
    sgemm128<<<dim3(2, 64), 256, 0, s1>>>(inp, Wv, bv, p_value, 256);
    cudaEventRecord(evJoin, s1);

    // main stream: proj (-> g_loc, g_attw, g_key init), then KNN (atomicMin)
    sgemm_nt<1><<<dim3(2, 32), 256>>>(query, Ws, Wa, 96, bs, ba,
                                      nullptr, 128, qpts);
    knn_kernel<<<256, 256>>>(ipts);

    // join: gather needs knn keys and g_value
    cudaStreamWaitEvent(0, evJoin, 0);
    gather_kernel<<<2048, 256>>>();
    // output projection: proven 64x64 tiles
    sgemm_nt<0><<<dim3(4, 32), 256>>>(p_mid, Wo, Wo, BIG, bo, bo,
                                      out, 256, nullptr);
}